// round 2
// baseline (speedup 1.0000x reference)
#include <cuda_runtime.h>

#define C_DIM 512
#define L_DIM 2048
#define BATCH 4
#define HEADS 8
#define HDIM 64

// Scratch (allocation-free rule: __device__ globals)
__device__ float g_qkv[BATCH * 3 * C_DIM * L_DIM]; // [B,3C,L]
__device__ float g_att[BATCH * C_DIM * L_DIM];     // attention out [B,C,L]
__device__ float g_z[BATCH * C_DIM * L_DIM];       // proj + bias + residual

// ---------------------------------------------------------------------------
// Tiled SGEMM: C[b] = A[MxK] * B[b][KxN] (+bias[m]) (optional clip) (optional +res)
// BM=BN=128, BK=8, 256 threads, 8x8 microtile (split 4+4 for conflict-free LDS)
// ---------------------------------------------------------------------------
template<bool CLIP, bool RES>
__global__ __launch_bounds__(256, 2) void sgemm_kernel(
    const float* __restrict__ A, const float* __restrict__ B, float* __restrict__ Cmat,
    const float* __restrict__ bias, const float* __restrict__ res,
    int M, int N, int K, int strideB, int strideC)
{
    __shared__ float As[8][128];
    __shared__ float Bs[8][128];
    const int t = threadIdx.x;
    const int tx = t & 15, ty = t >> 4;
    const int n0 = blockIdx.x * 128, m0 = blockIdx.y * 128;
    const float* Bp = B + (size_t)blockIdx.z * strideB;
    float* Cp = Cmat + (size_t)blockIdx.z * strideC;
    const float* Rp = RES ? (res + (size_t)blockIdx.z * strideB) : nullptr;

    const int arow = t >> 1, acol = (t & 1) * 4;
    const int brow = t >> 5, bcol = (t & 31) * 4;
    const float* Aptr = A + (size_t)(m0 + arow) * K + acol;
    const float* Bptr = Bp + (size_t)brow * N + n0 + bcol;

    float acc[8][8] = {};
    for (int k0 = 0; k0 < K; k0 += 8) {
        float4 av = *(const float4*)(Aptr + k0);
        float4 bv = *(const float4*)(Bptr + (size_t)k0 * N);
        As[acol + 0][arow] = av.x;
        As[acol + 1][arow] = av.y;
        As[acol + 2][arow] = av.z;
        As[acol + 3][arow] = av.w;
        *(float4*)&Bs[brow][bcol] = bv;
        __syncthreads();
        #pragma unroll
        for (int kk = 0; kk < 8; kk++) {
            float a[8], b[8];
            *(float4*)&a[0] = *(float4*)&As[kk][ty * 4];
            *(float4*)&a[4] = *(float4*)&As[kk][64 + ty * 4];
            *(float4*)&b[0] = *(float4*)&Bs[kk][tx * 4];
            *(float4*)&b[4] = *(float4*)&Bs[kk][64 + tx * 4];
            #pragma unroll
            for (int r = 0; r < 8; r++)
                #pragma unroll
                for (int c = 0; c < 8; c++)
                    acc[r][c] += a[r] * b[c];
        }
        __syncthreads();
    }

    #pragma unroll
    for (int r = 0; r < 8; r++) {
        int m = m0 + (r >> 2) * 64 + ty * 4 + (r & 3);
        float bvl = bias[m];
        #pragma unroll
        for (int ch = 0; ch < 2; ch++) {
            int n = n0 + ch * 64 + tx * 4;
            float4 o;
            o.x = acc[r][ch * 4 + 0] + bvl;
            o.y = acc[r][ch * 4 + 1] + bvl;
            o.z = acc[r][ch * 4 + 2] + bvl;
            o.w = acc[r][ch * 4 + 3] + bvl;
            if (CLIP) {
                o.x = fminf(10.f, fmaxf(-10.f, o.x));
                o.y = fminf(10.f, fmaxf(-10.f, o.y));
                o.z = fminf(10.f, fmaxf(-10.f, o.z));
                o.w = fminf(10.f, fmaxf(-10.f, o.w));
            }
            if (RES) {
                float4 rv = *(const float4*)(Rp + (size_t)m * N + n);
                o.x += rv.x; o.y += rv.y; o.z += rv.z; o.w += rv.w;
            }
            *(float4*)(Cp + (size_t)m * N + n) = o;
        }
    }
}

// ---------------------------------------------------------------------------
// Flash-style attention. Block = 64 queries for one (b,h). 256 threads.
// Clip of S to [-10,10] before softmax => exp() cannot overflow => no
// online-max needed; per-row denominators reduced once at the end.
// smem: Q[d][i], K[d][j] (reused for V^T[j][d]), P[i][j]  = 48KB exactly.
// ---------------------------------------------------------------------------
__global__ __launch_bounds__(256) void attn_kernel(
    const float* __restrict__ qkv, float* __restrict__ outp)
{
    __shared__ float qs[64 * 64];
    __shared__ float kv[64 * 64];
    __shared__ float ps[64 * 64];
    const int t = threadIdx.x;
    const int tx = t & 15, ty = t >> 4;
    const int b = blockIdx.z, h = blockIdx.y;
    const int i0 = blockIdx.x * 64;
    const float* qp = qkv + ((size_t)(b * 3 * C_DIM) + h * HDIM) * L_DIM;
    const float* kp = qp + (size_t)C_DIM * L_DIM;
    const float* vp = qp + (size_t)2 * C_DIM * L_DIM;

    // Q tile: qs[d*64 + i]
    {
        int lr = t >> 4, lc = (t & 15) * 4;
        #pragma unroll
        for (int it = 0; it < 4; it++) {
            int d = lr + it * 16;
            *(float4*)&qs[d * 64 + lc] = *(const float4*)&qp[(size_t)d * L_DIM + i0 + lc];
        }
    }

    float lp[4] = {0.f, 0.f, 0.f, 0.f};
    float oacc[4][4] = {};
    const float scale = 0.125f; // D^-0.5

    for (int j0 = 0; j0 < L_DIM; j0 += 64) {
        __syncthreads(); // prev O-phase done reading kv
        // K tile: kv[d*64 + j]
        {
            int lr = t >> 4, lc = (t & 15) * 4;
            #pragma unroll
            for (int it = 0; it < 4; it++) {
                int d = lr + it * 16;
                *(float4*)&kv[d * 64 + lc] = *(const float4*)&kp[(size_t)d * L_DIM + j0 + lc];
            }
        }
        __syncthreads();

        // S = Q^T K  (thread: i = ty*4+r, j = tx*4+c)
        float s[4][4] = {};
        #pragma unroll
        for (int d = 0; d < 64; d++) {
            float4 qv = *(float4*)&qs[d * 64 + ty * 4];
            float4 kk = *(float4*)&kv[d * 64 + tx * 4];
            s[0][0] += qv.x * kk.x; s[0][1] += qv.x * kk.y; s[0][2] += qv.x * kk.z; s[0][3] += qv.x * kk.w;
            s[1][0] += qv.y * kk.x; s[1][1] += qv.y * kk.y; s[1][2] += qv.y * kk.z; s[1][3] += qv.y * kk.w;
            s[2][0] += qv.z * kk.x; s[2][1] += qv.z * kk.y; s[2][2] += qv.z * kk.z; s[2][3] += qv.z * kk.w;
            s[3][0] += qv.w * kk.x; s[3][1] += qv.w * kk.y; s[3][2] += qv.w * kk.z; s[3][3] += qv.w * kk.w;
        }
        // scale, clip, exp; accumulate row partial sums; stage P
        #pragma unroll
        for (int r = 0; r < 4; r++) {
            float4 p;
            p.x = __expf(fminf(10.f, fmaxf(-10.f, s[r][0] * scale)));
            p.y = __expf(fminf(10.f, fmaxf(-10.f, s[r][1] * scale)));
            p.z = __expf(fminf(10.f, fmaxf(-10.f, s[r][2] * scale)));
            p.w = __expf(fminf(10.f, fmaxf(-10.f, s[r][3] * scale)));
            lp[r] += p.x + p.y + p.z + p.w;
            *(float4*)&ps[(ty * 4 + r) * 64 + tx * 4] = p;
        }
        __syncthreads(); // S-phase reads of kv done; ps visible

        // V tile transposed: kv[j*64 + d]  (lanes -> consecutive d: conflict-free STS)
        {
            int dd = t & 63;
            int jc = (t >> 6) * 4; // 0,4,8,12
            #pragma unroll
            for (int it = 0; it < 4; it++) {
                int j = jc + it * 16;
                float4 vv = *(const float4*)&vp[(size_t)dd * L_DIM + j0 + j];
                kv[(j + 0) * 64 + dd] = vv.x;
                kv[(j + 1) * 64 + dd] = vv.y;
                kv[(j + 2) * 64 + dd] = vv.z;
                kv[(j + 3) * 64 + dd] = vv.w;
            }
        }
        __syncthreads();

        // O[i][d] += sum_j P[i][j] * V[d][j]  (thread: i = ty*4+r, d = tx*4+c)
        #pragma unroll 16
        for (int j = 0; j < 64; j++) {
            float4 vv = *(float4*)&kv[j * 64 + tx * 4];
            float p0 = ps[(ty * 4 + 0) * 64 + j];
            float p1 = ps[(ty * 4 + 1) * 64 + j];
            float p2 = ps[(ty * 4 + 2) * 64 + j];
            float p3 = ps[(ty * 4 + 3) * 64 + j];
            oacc[0][0] += p0 * vv.x; oacc[0][1] += p0 * vv.y; oacc[0][2] += p0 * vv.z; oacc[0][3] += p0 * vv.w;
            oacc[1][0] += p1 * vv.x; oacc[1][1] += p1 * vv.y; oacc[1][2] += p1 * vv.z; oacc[1][3] += p1 * vv.w;
            oacc[2][0] += p2 * vv.x; oacc[2][1] += p2 * vv.y; oacc[2][2] += p2 * vv.z; oacc[2][3] += p2 * vv.w;
            oacc[3][0] += p3 * vv.x; oacc[3][1] += p3 * vv.y; oacc[3][2] += p3 * vv.z; oacc[3][3] += p3 * vv.w;
        }
    }

    // Row denominators: reduce across the 16 tx lanes (width-16 groups align with ty)
    #pragma unroll
    for (int r = 0; r < 4; r++) {
        float v = lp[r];
        #pragma unroll
        for (int o = 8; o; o >>= 1) v += __shfl_xor_sync(0xffffffffu, v, o, 16);
        lp[r] = 1.0f / v;
    }

    // Write O: per c, pack 4 consecutive i into one float4 (coalesced 32B runs)
    float* ob = outp + ((size_t)(b * C_DIM) + h * HDIM) * L_DIM;
    #pragma unroll
    for (int c = 0; c < 4; c++) {
        int d = tx * 4 + c;
        float4 o4;
        o4.x = oacc[0][c] * lp[0];
        o4.y = oacc[1][c] * lp[1];
        o4.z = oacc[2][c] * lp[2];
        o4.w = oacc[3][c] * lp[3];
        *(float4*)&ob[(size_t)d * L_DIM + i0 + ty * 4] = o4;
    }
}

// ---------------------------------------------------------------------------
// GroupNorm over z (residual already fused). One block per (b, group).
// Group = 16 channels x 2048 = 32768 elems.
// ---------------------------------------------------------------------------
__global__ __launch_bounds__(256) void gn_kernel(
    const float* __restrict__ z, const float* __restrict__ gamma,
    const float* __restrict__ beta, float* __restrict__ outp)
{
    const int bg = blockIdx.x;
    const int b = bg >> 5, g = bg & 31;
    const float* zp = z + ((size_t)b * C_DIM + g * 16) * L_DIM;
    float* op = outp + ((size_t)b * C_DIM + g * 16) * L_DIM;
    const int t = threadIdx.x;

    float s = 0.f, ss = 0.f;
    const float4* z4 = (const float4*)zp;
    for (int i = t; i < 8192; i += 256) {
        float4 v = z4[i];
        s  += v.x + v.y + v.z + v.w;
        ss += v.x * v.x + v.y * v.y + v.z * v.z + v.w * v.w;
    }
    __shared__ float rs[8], rss[8];
    __shared__ float smu, srstd;
    #pragma unroll
    for (int o = 16; o; o >>= 1) {
        s  += __shfl_xor_sync(0xffffffffu, s, o);
        ss += __shfl_xor_sync(0xffffffffu, ss, o);
    }
    if ((t & 31) == 0) { rs[t >> 5] = s; rss[t >> 5] = ss; }
    __syncthreads();
    if (t == 0) {
        float ts = 0.f, tss = 0.f;
        #pragma unroll
        for (int w = 0; w < 8; w++) { ts += rs[w]; tss += rss[w]; }
        float mu = ts * (1.f / 32768.f);
        float var = tss * (1.f / 32768.f) - mu * mu;
        smu = mu;
        srstd = rsqrtf(var + 1e-5f);
    }
    __syncthreads();
    const float mu = smu, rstd = srstd;
    float4* o4 = (float4*)op;
    for (int i = t; i < 8192; i += 256) {
        int ch = g * 16 + (i >> 9); // 512 float4 per channel row
        float ga = gamma[ch] * rstd;
        float be = beta[ch];
        float4 v = z4[i];
        v.x = (v.x - mu) * ga + be;
        v.y = (v.y - mu) * ga + be;
        v.z = (v.z - mu) * ga + be;
        v.w = (v.w - mu) * ga + be;
        o4[i] = v;
    }
}

// ---------------------------------------------------------------------------
extern "C" void kernel_launch(void* const* d_in, const int* in_sizes, int n_in,
                              void* d_out, int out_size)
{
    const float* x     = (const float*)d_in[0];
    const float* Wqkv  = (const float*)d_in[1];
    const float* bqkv  = (const float*)d_in[2];
    const float* Wproj = (const float*)d_in[3];
    const float* bproj = (const float*)d_in[4];
    const float* gamma = (const float*)d_in[5];
    const float* beta  = (const float*)d_in[6];
    float* out = (float*)d_out;

    float *qkv, *att, *zbuf;
    cudaGetSymbolAddress((void**)&qkv,  g_qkv);
    cudaGetSymbolAddress((void**)&att,  g_att);
    cudaGetSymbolAddress((void**)&zbuf, g_z);

    const int CL = C_DIM * L_DIM;
    dim3 blk(256);

    // qkv = Wqkv @ x + bqkv, clipped to [-10,10]
    sgemm_kernel<true, false><<<dim3(16, 12, BATCH), blk>>>(
        Wqkv, x, qkv, bqkv, nullptr, 3 * C_DIM, L_DIM, C_DIM, CL, 3 * CL);

    // attention
    attn_kernel<<<dim3(32, HEADS, BATCH), blk>>>(qkv, att);

    // z = Wproj @ att + bproj + x
    sgemm_kernel<false, true><<<dim3(16, 4, BATCH), blk>>>(
        Wproj, att, zbuf, bproj, x, C_DIM, L_DIM, C_DIM, CL, CL);

    // out = groupnorm(z)
    gn_kernel<<<dim3(BATCH * 32), blk>>>(zbuf, gamma, beta, out);
}